// round 6
// baseline (speedup 1.0000x reference)
#include <cuda_runtime.h>
#include <cstdint>
#include <cstddef>

// Problem constants
#define BB   128      // batch
#define TT   2048     // timesteps
#define UU   256      // units
#define CLS  8        // cluster size (u-split)
#define BPC  8        // batches per cluster
#define UCTA 32       // u per CTA
#define COLS 128      // z columns per CTA; c = u*4 + g  (gate-minor layout!)
#define NTHR 1024     // 32 warps: 128 cols x 8 k-splits
#define KSPL 8
#define KPT  32       // k per thread

// Dynamic shared memory layout (bytes)
#define OFF_H    0                          // h double buffer [2][8][256] f32 (16 KB)
#define OFF_Z    (OFF_H  + 2*BPC*UU*4)      // zpart [2][KSPL][BPC][COLS] f32 (64 KB)
#define OFF_WX   (OFF_Z  + 2*KSPL*BPC*COLS*4)
#define OFF_BI   (OFF_WX + 3*COLS*4)
#define OFF_XS   (OFF_BI + COLS*4)          // xss [2][8][4] f32
#define OFF_MB   (OFF_XS + 2*BPC*4*4)       // 2 mbarriers
#define SMEM_BYTES (OFF_MB + 64)

typedef unsigned long long ull;

__device__ __forceinline__ void ffma2(ull &acc, ull a, ull w) {
    asm("fma.rn.f32x2 %0, %1, %2, %0;" : "+l"(acc) : "l"(a), "l"(w));
}

__device__ __forceinline__ uint32_t smem_u32(const void* p) {
    uint32_t a;
    asm("{ .reg .u64 t; cvta.to.shared.u64 t, %1; cvt.u32.u64 %0, t; }"
        : "=r"(a) : "l"(p));
    return a;
}

// b64 store into CTA `rank`'s smem, signaling that CTA's mbarrier with 8 tx bytes.
__device__ __forceinline__ void st_async_h64(uint32_t daddr, uint32_t mbar,
                                             uint32_t rank, ull v) {
    uint32_t ra, rm;
    asm volatile("mapa.shared::cluster.u32 %0, %1, %2;" : "=r"(ra) : "r"(daddr), "r"(rank));
    asm volatile("mapa.shared::cluster.u32 %0, %1, %2;" : "=r"(rm) : "r"(mbar), "r"(rank));
    asm volatile("st.async.shared::cluster.mbarrier::complete_tx::bytes.b64 [%0], %1, [%2];"
                 :: "r"(ra), "l"(v), "r"(rm) : "memory");
}

__device__ __forceinline__ void mbar_init(uint32_t mbar, uint32_t cnt) {
    asm volatile("mbarrier.init.shared.b64 [%0], %1;" :: "r"(mbar), "r"(cnt) : "memory");
}
__device__ __forceinline__ void mbar_arrive_expect(uint32_t mbar, uint32_t tx) {
    asm volatile("mbarrier.arrive.expect_tx.shared.b64 _, [%0], %1;"
                 :: "r"(mbar), "r"(tx) : "memory");
}
__device__ __forceinline__ void mbar_wait(uint32_t mbar, uint32_t parity) {
    asm volatile(
        "{\n\t"
        ".reg .pred P;\n\t"
        "WL_%=:\n\t"
        "mbarrier.try_wait.parity.acquire.cta.shared::cta.b64 P, [%0], %1, 0x989680;\n\t"
        "@P bra.uni WD_%=;\n\t"
        "bra.uni WL_%=;\n\t"
        "WD_%=:\n\t"
        "}" :: "r"(mbar), "r"(parity) : "memory");
}

__device__ __forceinline__ float sigm(float v) { return 1.f / (1.f + __expf(-v)); }
__device__ __forceinline__ float tanh_f(float v) {
    float vv = fminf(fmaxf(v, -15.f), 15.f);
    float e = __expf(-2.f * vv);
    return (1.f - e) / (1.f + e);
}

__global__ void __launch_bounds__(NTHR, 1) __cluster_dims__(CLS, 1, 1)
lstm_cluster_kernel(const float* __restrict__ x,     // [B,T,3]
                    const float* __restrict__ Wx,    // [3,1024]
                    const float* __restrict__ Wh,    // [256,1024]
                    const float* __restrict__ bias,  // [1024]
                    float* __restrict__ out, int out_size)
{
    extern __shared__ char sm[];
    float* hbuf  = (float*)(sm + OFF_H);    // [2][BPC][UU]
    float* zpart = (float*)(sm + OFF_Z);    // [2][KSPL][BPC][COLS]
    float* wxs   = (float*)(sm + OFF_WX);   // [3][COLS]
    float* bis   = (float*)(sm + OFF_BI);   // [COLS]
    float* xss   = (float*)(sm + OFF_XS);   // [2][BPC][4]

    const int tid   = threadIdx.x;
    const int crank = blockIdx.x & (CLS - 1);
    const int cid   = blockIdx.x >> 3;
    const int bBase = cid * BPC;
    const int uBase = crank * UCTA;

    const uint32_t mb0 = smem_u32(sm + OFF_MB);
    const uint32_t mb1 = mb0 + 8;

    // Column label c = u*4 + g  (gate-minor). Its Wh/Wx/bias column:
    const int c  = tid & 127;
    const int kh = tid >> 7;                 // k-split 0..7
    const int cu = c >> 2, cg = c & 3;
    const int gcol = cg * UU + uBase + cu;

    // ---- Prologue ----
    // Wh slice into registers: 16 f32x2 pairs, k in [kh*32, kh*32+32)
    ull wq[KPT / 2];
    {
        const int k0 = kh * KPT;
        #pragma unroll
        for (int j = 0; j < KPT / 2; ++j) {
            float2 p = make_float2(Wh[(size_t)(k0 + 2 * j) * 1024 + gcol],
                                   Wh[(size_t)(k0 + 2 * j + 1) * 1024 + gcol]);
            wq[j] = *(ull*)&p;
        }
    }
    for (int idx = tid; idx < 3 * COLS; idx += NTHR) {
        int f = idx >> 7, cc = idx & 127;
        wxs[idx] = Wx[f * 1024 + (cc & 3) * UU + uBase + (cc >> 2)];
    }
    if (tid < COLS) bis[tid] = bias[(tid & 3) * UU + uBase + (tid >> 2)];
    for (int idx = tid; idx < 2 * BPC * UU; idx += NTHR) hbuf[idx] = 0.f;
    if (tid == 0) {
        mbar_init(mb0, 1);
        mbar_init(mb1, 1);
        mbar_arrive_expect(mb0, BPC * UU * 4);   // 8 KB per phase per buffer
        mbar_arrive_expect(mb1, BPC * UU * 4);
    }
    __syncthreads();
    asm volatile("barrier.cluster.arrive.aligned;" ::: "memory");
    asm volatile("barrier.cluster.wait.aligned;"   ::: "memory");

    // Epilogue mapping: thread -> (batch eb, unit cu, gate cg); column == c.
    const int eb = tid >> 7;                 // 0..7
    const int gu = uBase + cu;
    const int gb = bBase + eb;
    const int lane = tid & 31;
    const int lbase = lane & ~3;
    // h broadcast source threads: cg==0 && even cu; they pack (h[cu], h[cu+1])
    const uint32_t haddr0 = smem_u32(hbuf + 0 * BPC * UU + eb * UU + gu);
    const uint32_t haddr1 = smem_u32(hbuf + 1 * BPC * UU + eb * UU + gu);

    float creg = 0.f, hreg = 0.f;
    uint32_t ph0 = 0, ph1 = 0;

    for (int t = 0; t < TT; ++t) {
        const int pp = t & 1;

        // x prefetch (24 threads)
        float xv = 0.f; int xb = 0, xf = 0;
        if (tid < BPC * 3) {
            xb = tid / 3; xf = tid - xb * 3;
            xv = x[((size_t)(bBase + xb) * TT + t) * 3 + xf];
        }

        // wait for this step's h buffer, re-arm for step t+2
        if (t > 0) {
            uint32_t mb = pp ? mb1 : mb0;
            uint32_t ph = pp ? ph1 : ph0;
            mbar_wait(mb, ph);
            if (pp) ph1 ^= 1; else ph0 ^= 1;
            if (tid == 0) mbar_arrive_expect(mb, BPC * UU * 4);
        }

        // ---- GEMM: zpart[pp][kh][b][c] = sum_{k in 32-slice} h[b][k] * W[k][c] ----
        const float4* __restrict__ h4 = (const float4*)(hbuf + pp * BPC * UU);
        const int qbase = kh * 8;            // float4 index of this k-slice
        float* __restrict__ zp = zpart + ((pp * KSPL + kh) * BPC) * COLS + c;
        #pragma unroll
        for (int grp = 0; grp < 2; ++grp) {
            ull a0 = 0ull, a1 = 0ull, a2 = 0ull, a3 = 0ull;
            const float4* __restrict__ hg = h4 + (grp * 4) * 64 + qbase;
            #pragma unroll
            for (int q = 0; q < 8; ++q) {
                ull w0 = wq[2 * q], w1 = wq[2 * q + 1];
                float4 v0 = hg[0 * 64 + q];
                float4 v1 = hg[1 * 64 + q];
                float4 v2 = hg[2 * 64 + q];
                float4 v3 = hg[3 * 64 + q];
                ffma2(a0, *(ull*)&v0, w0); ffma2(a0, *((ull*)&v0 + 1), w1);
                ffma2(a1, *(ull*)&v1, w0); ffma2(a1, *((ull*)&v1 + 1), w1);
                ffma2(a2, *(ull*)&v2, w0); ffma2(a2, *((ull*)&v2 + 1), w1);
                ffma2(a3, *(ull*)&v3, w0); ffma2(a3, *((ull*)&v3 + 1), w1);
            }
            { float2 f = *(float2*)&a0; zp[(grp * 4 + 0) * COLS] = f.x + f.y; }
            { float2 f = *(float2*)&a1; zp[(grp * 4 + 1) * COLS] = f.x + f.y; }
            { float2 f = *(float2*)&a2; zp[(grp * 4 + 2) * COLS] = f.x + f.y; }
            { float2 f = *(float2*)&a3; zp[(grp * 4 + 3) * COLS] = f.x + f.y; }
        }
        if (tid < BPC * 3) xss[(pp * BPC + xb) * 4 + xf] = xv;
        __syncthreads();

        // ---- epilogue: ALL threads; one gate per thread, gather via shfl ----
        {
            const float* xr = xss + (pp * BPC + eb) * 4;
            float x0 = xr[0], x1 = xr[1], x2 = xr[2];
            const float* zb = zpart + (pp * KSPL * BPC) * COLS + eb * COLS + c;
            float z = bis[c] + x0 * wxs[c] + x1 * wxs[COLS + c] + x2 * wxs[2 * COLS + c];
            #pragma unroll
            for (int k = 0; k < KSPL; ++k) z += zb[k * BPC * COLS];

            // gate order in z-column layout: cg = 0:i 1:f 2:g 3:o
            float a = (cg == 2) ? tanh_f(z) : sigm(z);
            const unsigned m = 0xFFFFFFFFu;
            float vi = __shfl_sync(m, a, lbase | 0);
            float vf = __shfl_sync(m, a, lbase | 1);
            float vg = __shfl_sync(m, a, lbase | 2);
            float vo = __shfl_sync(m, a, lbase | 3);
            creg = vf * creg + vi * vg;            // identical in all 4 gate lanes
            hreg = vo * tanh_f(creg);

            // pack (h[cu], h[cu+1]) from lane+4 and broadcast as b64
            float hn = __shfl_sync(m, hreg, (lane + 4) & 31);
            if (cg == 0) {
                if ((cu & 1) == 0) {
                    float2 hp = make_float2(hreg, hn);
                    ull hv = *(ull*)&hp;
                    uint32_t hdst = pp ? haddr0 : haddr1;  // next buffer
                    uint32_t mbn  = pp ? mb0 : mb1;
                    #pragma unroll
                    for (uint32_t r = 0; r < CLS; ++r) st_async_h64(hdst, mbn, r, hv);
                    // coalesced-ish output store: ys[b][t][cu..cu+1]
                    *(float2*)&out[((size_t)gb * TT + t) * UU + gu] = hp;
                }
            }
        }
    }

    // keep all cluster CTAs alive until the last in-flight st.async lands
    asm volatile("barrier.cluster.arrive.aligned;" ::: "memory");
    asm volatile("barrier.cluster.wait.aligned;"   ::: "memory");

    if (cg == 0 && out_size >= BB * TT * UU + 2 * BB * UU) {
        size_t base = (size_t)BB * TT * UU;
        out[base + (size_t)gb * UU + gu] = hreg;
        out[base + (size_t)BB * UU + (size_t)gb * UU + gu] = creg;
    }
}

extern "C" void kernel_launch(void* const* d_in, const int* in_sizes, int n_in,
                              void* d_out, int out_size)
{
    const float* x  = nullptr;  // 786432
    const float* wx = nullptr;  // 3072
    const float* wh = nullptr;  // 262144
    const float* bi = nullptr;  // 1024
    for (int i = 0; i < n_in; ++i) {
        switch (in_sizes[i]) {
            case 786432: x  = (const float*)d_in[i]; break;
            case 3072:   wx = (const float*)d_in[i]; break;
            case 262144: wh = (const float*)d_in[i]; break;
            case 1024:   bi = (const float*)d_in[i]; break;
            default: break;
        }
    }
    if (!x)  x  = (const float*)d_in[0];
    if (!wx) wx = (const float*)d_in[1];
    if (!wh) wh = (const float*)d_in[2];
    if (!bi) bi = (const float*)d_in[3];

    cudaFuncSetAttribute(lstm_cluster_kernel,
                         cudaFuncAttributeMaxDynamicSharedMemorySize, SMEM_BYTES);

    lstm_cluster_kernel<<<BB / BPC * CLS, NTHR, SMEM_BYTES>>>(
        x, wx, wh, bi, (float*)d_out, out_size);
}

// round 8
// speedup vs baseline: 1.3297x; 1.3297x over previous
#include <cuda_runtime.h>
#include <cstdint>
#include <cstddef>

// Problem constants
#define BB   128      // batch
#define TT   2048     // timesteps
#define UU   256      // units
#define CLS  8        // cluster size (u-split)
#define BPC  8        // batches per cluster
#define UCTA 32       // u per CTA
#define COLS 128      // z columns per CTA (gate-major: c = g*32 + u)
#define NTHR 512      // 16 warps
#define KSPL 8        // k-split factor (one 32-wide k slice per kh == source rank)
#define KPT  32       // k per thread slice
#define CPT  2        // columns per thread

// Dynamic shared memory layout (bytes)
#define OFF_H    0                            // hbuf [2][CLS][BPC][UCTA] f32 = 8 KB
#define SZ_H     (2*CLS*BPC*UCTA*4)
#define OFF_STG  (OFF_H + SZ_H)               // hstage [2][BPC][UCTA] f32 = 2 KB
#define SZ_STG   (2*BPC*UCTA*4)
#define OFF_Z    (OFF_STG + SZ_STG)           // zpart [KSPL][BPC][COLS] f32 = 32 KB
#define SZ_Z     (KSPL*BPC*COLS*4)
#define OFF_WX   (OFF_Z + SZ_Z)               // wxs [3][COLS]
#define OFF_BI   (OFF_WX + 3*COLS*4)          // bis [COLS]
#define OFF_XS   (OFF_BI + COLS*4)            // xss [BPC][4]
#define OFF_MB   (OFF_XS + BPC*4*4)           // 2 mbarriers
#define SMEM_BYTES (OFF_MB + 64)

#define H_BLOCK_BYTES (BPC*UCTA*4)            // 1024 B per CTA per step
#define TX_BYTES      (CLS*H_BLOCK_BYTES)     // 8192 B per buffer per phase

typedef unsigned long long ull;

__device__ __forceinline__ void ffma2(ull &acc, ull a, ull w) {
    asm("fma.rn.f32x2 %0, %1, %2, %0;" : "+l"(acc) : "l"(a), "l"(w));
}

__device__ __forceinline__ uint32_t smem_u32(const void* p) {
    uint32_t a;
    asm("{ .reg .u64 t; cvta.to.shared.u64 t, %1; cvt.u32.u64 %0, t; }"
        : "=r"(a) : "l"(p));
    return a;
}

__device__ __forceinline__ void mbar_init(uint32_t mbar, uint32_t cnt) {
    asm volatile("mbarrier.init.shared.b64 [%0], %1;" :: "r"(mbar), "r"(cnt) : "memory");
}
__device__ __forceinline__ void mbar_arrive_expect(uint32_t mbar, uint32_t tx) {
    asm volatile("mbarrier.arrive.expect_tx.shared.b64 _, [%0], %1;"
                 :: "r"(mbar), "r"(tx) : "memory");
}
__device__ __forceinline__ void mbar_wait(uint32_t mbar, uint32_t parity) {
    asm volatile(
        "{\n\t"
        ".reg .pred P;\n\t"
        "WL_%=:\n\t"
        "mbarrier.try_wait.parity.acquire.cta.shared::cta.b64 P, [%0], %1, 0x989680;\n\t"
        "@P bra.uni WD_%=;\n\t"
        "bra.uni WL_%=;\n\t"
        "WD_%=:\n\t"
        "}" :: "r"(mbar), "r"(parity) : "memory");
}

// DSMEM block copy: local smem -> peer CTA smem, signaling the PEER's mbarrier
// with `bytes` of transaction count.
__device__ __forceinline__ void bulk_copy_to_rank(uint32_t dst_local, uint32_t src,
                                                  uint32_t bytes, uint32_t mbar_local,
                                                  uint32_t rank) {
    uint32_t rd, rm;
    asm volatile("mapa.shared::cluster.u32 %0, %1, %2;" : "=r"(rd) : "r"(dst_local), "r"(rank));
    asm volatile("mapa.shared::cluster.u32 %0, %1, %2;" : "=r"(rm) : "r"(mbar_local), "r"(rank));
    asm volatile("cp.async.bulk.shared::cluster.shared::cta.mbarrier::complete_tx::bytes "
                 "[%0], [%1], %2, [%3];"
                 :: "r"(rd), "r"(src), "r"(bytes), "r"(rm) : "memory");
}

__device__ __forceinline__ float sigm(float v) { return 1.f / (1.f + __expf(-v)); }
__device__ __forceinline__ float tanh_f(float v) {
    float vv = fminf(fmaxf(v, -15.f), 15.f);
    float e = __expf(-2.f * vv);
    return (1.f - e) / (1.f + e);
}

__global__ void __launch_bounds__(NTHR, 1) __cluster_dims__(CLS, 1, 1)
lstm_cluster_kernel(const float* __restrict__ x,     // [B,T,3]
                    const float* __restrict__ Wx,    // [3,1024]
                    const float* __restrict__ Wh,    // [256,1024]
                    const float* __restrict__ bias,  // [1024]
                    float* __restrict__ out, int out_size)
{
    extern __shared__ char sm[];
    float* hbuf   = (float*)(sm + OFF_H);    // [2][CLS rank][BPC][UCTA]; k = rank*32+u
    float* hstage = (float*)(sm + OFF_STG);  // [2][BPC][UCTA]
    float* zpart  = (float*)(sm + OFF_Z);    // [KSPL][BPC][COLS]
    float* wxs    = (float*)(sm + OFF_WX);   // [3][COLS]
    float* bis    = (float*)(sm + OFF_BI);   // [COLS]
    float* xss    = (float*)(sm + OFF_XS);   // [BPC][4]

    const int tid   = threadIdx.x;
    const int crank = blockIdx.x & (CLS - 1);
    const int cid   = blockIdx.x >> 3;
    const int bBase = cid * BPC;
    const int uBase = crank * UCTA;

    const uint32_t mb0 = smem_u32(sm + OFF_MB);
    const uint32_t mb1 = mb0 + 8;
    const uint32_t stg0 = smem_u32(hstage);                       // staging, buffer 0
    const uint32_t hdst_base = smem_u32(hbuf) + crank * H_BLOCK_BYTES; // our block in buffer 0

    // GEMM mapping: kh = k slice (== producer rank), two columns per thread
    const int kh   = tid >> 6;               // 0..7
    const int sub  = (tid >> 5) & 1;         // 0..1
    const int lane = tid & 31;
    const int c0   = sub * 32 + lane;        // 0..63
    const int c1   = c0 + 64;                // 64..127

    // ---- Prologue: weights into registers ----
    ull wq0[KPT / 2], wq1[KPT / 2];
    {
        const int k0 = kh * KPT;
        const int gcolA = (c0 >> 5) * UU + uBase + (c0 & 31);
        const int gcolB = (c1 >> 5) * UU + uBase + (c1 & 31);
        #pragma unroll
        for (int j = 0; j < KPT / 2; ++j) {
            float2 pa = make_float2(Wh[(size_t)(k0 + 2 * j) * 1024 + gcolA],
                                    Wh[(size_t)(k0 + 2 * j + 1) * 1024 + gcolA]);
            float2 pb = make_float2(Wh[(size_t)(k0 + 2 * j) * 1024 + gcolB],
                                    Wh[(size_t)(k0 + 2 * j + 1) * 1024 + gcolB]);
            wq0[j] = *(ull*)&pa;
            wq1[j] = *(ull*)&pb;
        }
    }
    for (int idx = tid; idx < 3 * COLS; idx += NTHR) {
        int f = idx >> 7, cc = idx & 127;
        wxs[idx] = Wx[f * 1024 + (cc >> 5) * UU + uBase + (cc & 31)];
    }
    if (tid < COLS) bis[tid] = bias[(tid >> 5) * UU + uBase + (tid & 31)];
    for (int idx = tid; idx < 2 * CLS * BPC * UCTA; idx += NTHR) hbuf[idx] = 0.f;
    if (tid == 0) {
        mbar_init(mb0, 1);
        mbar_init(mb1, 1);
        mbar_arrive_expect(mb0, TX_BYTES);
        mbar_arrive_expect(mb1, TX_BYTES);
    }
    __syncthreads();
    asm volatile("barrier.cluster.arrive.aligned;" ::: "memory");
    asm volatile("barrier.cluster.wait.aligned;"   ::: "memory");

    // Epilogue mapping (threads 0..255): (batch eb, unit eu), gate-major columns
    const int eb = tid >> 5;
    const int eu = tid & 31;
    const int gu = uBase + eu;
    const int gb = bBase + (eb & 7);

    float creg = 0.f, hreg = 0.f;
    uint32_t ph0 = 0, ph1 = 0;

    for (int t = 0; t < TT; ++t) {
        const int pp = t & 1;
        const int np = pp ^ 1;

        // x prefetch (24 threads), LDG issued before the release barrier
        float xv = 0.f; int xb = 0, xf = 0;
        if (tid < BPC * 3) {
            xb = tid / 3; xf = tid - xb * 3;
            xv = x[((size_t)(bBase + xb) * TT + t) * 3 + xf];
        }

        // Single-thread wait on this step's h buffer; re-arm for the next phase.
        if (t > 0) {
            if (tid == 0) {
                uint32_t mb = pp ? mb1 : mb0;
                mbar_wait(mb, pp ? ph1 : ph0);
                mbar_arrive_expect(mb, TX_BYTES);
            }
            if (pp) ph1 ^= 1; else ph0 ^= 1;
        }
        __syncthreads();   // bar1: release h buffer to all warps

        // ---- GEMM: zpart[kh][b][c] over this thread's 32-wide k slice ----
        // h for slice kh lives in hbuf[pp][kh][b][0..31] (contiguous per b).
        const float4* __restrict__ h4 =
            (const float4*)(hbuf + (pp * CLS + kh) * BPC * UCTA);  // [b][8]
        #pragma unroll
        for (int grp = 0; grp < 2; ++grp) {
            ull p0 = 0ull, p1 = 0ull, p2 = 0ull, p3 = 0ull;   // col c0, b 0..3
            ull q0 = 0ull, q1 = 0ull, q2 = 0ull, q3 = 0ull;   // col c1
            const float4* __restrict__ hg = h4 + (grp * 4) * 8;
            #pragma unroll
            for (int q = 0; q < 8; ++q) {
                ull wa0 = wq0[2 * q], wa1 = wq0[2 * q + 1];
                ull wb0 = wq1[2 * q], wb1 = wq1[2 * q + 1];
                float4 v0 = hg[0 * 8 + q];
                float4 v1 = hg[1 * 8 + q];
                float4 v2 = hg[2 * 8 + q];
                float4 v3 = hg[3 * 8 + q];
                ull l0 = *(ull*)&v0, h0 = *((ull*)&v0 + 1);
                ull l1 = *(ull*)&v1, h1 = *((ull*)&v1 + 1);
                ull l2 = *(ull*)&v2, h2 = *((ull*)&v2 + 1);
                ull l3 = *(ull*)&v3, h3 = *((ull*)&v3 + 1);
                ffma2(p0, l0, wa0); ffma2(p0, h0, wa1);
                ffma2(p1, l1, wa0); ffma2(p1, h1, wa1);
                ffma2(p2, l2, wa0); ffma2(p2, h2, wa1);
                ffma2(p3, l3, wa0); ffma2(p3, h3, wa1);
                ffma2(q0, l0, wb0); ffma2(q0, h0, wb1);
                ffma2(q1, l1, wb0); ffma2(q1, h1, wb1);
                ffma2(q2, l2, wb0); ffma2(q2, h2, wb1);
                ffma2(q3, l3, wb0); ffma2(q3, h3, wb1);
            }
            float* zp = zpart + kh * BPC * COLS + (grp * 4) * COLS;
            { float2 f = *(float2*)&p0; zp[0 * COLS + c0] = f.x + f.y; }
            { float2 f = *(float2*)&p1; zp[1 * COLS + c0] = f.x + f.y; }
            { float2 f = *(float2*)&p2; zp[2 * COLS + c0] = f.x + f.y; }
            { float2 f = *(float2*)&p3; zp[3 * COLS + c0] = f.x + f.y; }
            { float2 f = *(float2*)&q0; zp[0 * COLS + c1] = f.x + f.y; }
            { float2 f = *(float2*)&q1; zp[1 * COLS + c1] = f.x + f.y; }
            { float2 f = *(float2*)&q2; zp[2 * COLS + c1] = f.x + f.y; }
            { float2 f = *(float2*)&q3; zp[3 * COLS + c1] = f.x + f.y; }
        }
        if (tid < BPC * 3) xss[xb * 4 + xf] = xv;
        __syncthreads();   // bar2: zpart + xss ready

        // ---- epilogue (threads 0..255): reduce + gates + state + stage ----
        if (tid < 256) {
            float x0 = xss[eb * 4 + 0], x1 = xss[eb * 4 + 1], x2 = xss[eb * 4 + 2];
            const float* zb = zpart + eb * COLS;
            float zg[4];
            #pragma unroll
            for (int g = 0; g < 4; ++g) {
                int cc = g * 32 + eu;
                float z = bis[cc] + x0 * wxs[cc] + x1 * wxs[COLS + cc] + x2 * wxs[2 * COLS + cc];
                #pragma unroll
                for (int k = 0; k < KSPL; ++k) z += zb[k * BPC * COLS + cc];
                zg[g] = z;
            }
            float ig = sigm(zg[0]);
            float fg = sigm(zg[1]);
            float gv = tanh_f(zg[2]);
            float og = sigm(zg[3]);
            creg = fg * creg + ig * gv;
            hreg = og * tanh_f(creg);

            hstage[(np * BPC + eb) * UCTA + eu] = hreg;   // contiguous 1 KB block
            out[((size_t)gb * TT + t) * UU + gu] = hreg;  // coalesced 128B per warp
        }
        __syncthreads();   // bar3: staging complete

        // ---- one thread broadcasts the 1 KB block to all 8 CTAs (incl. self) ----
        if (tid == 0) {
            asm volatile("fence.proxy.async.shared::cta;" ::: "memory");
            uint32_t src  = stg0 + np * H_BLOCK_BYTES;
            uint32_t dst  = hdst_base + np * CLS * H_BLOCK_BYTES;
            uint32_t mbn  = np ? mb1 : mb0;
            #pragma unroll
            for (uint32_t r = 0; r < CLS; ++r)
                bulk_copy_to_rank(dst, src, H_BLOCK_BYTES, mbn, r);
        }
    }

    // keep all cluster CTAs alive until last in-flight bulk copies land
    asm volatile("barrier.cluster.arrive.aligned;" ::: "memory");
    asm volatile("barrier.cluster.wait.aligned;"   ::: "memory");

    if (tid < 256 && out_size >= BB * TT * UU + 2 * BB * UU) {
        size_t base = (size_t)BB * TT * UU;
        out[base + (size_t)gb * UU + gu] = hreg;
        out[base + (size_t)BB * UU + (size_t)gb * UU + gu] = creg;
    }
}

extern "C" void kernel_launch(void* const* d_in, const int* in_sizes, int n_in,
                              void* d_out, int out_size)
{
    const float* x  = nullptr;  // 786432
    const float* wx = nullptr;  // 3072
    const float* wh = nullptr;  // 262144
    const float* bi = nullptr;  // 1024
    for (int i = 0; i < n_in; ++i) {
        switch (in_sizes[i]) {
            case 786432: x  = (const float*)d_in[i]; break;
            case 3072:   wx = (const float*)d_in[i]; break;
            case 262144: wh = (const float*)d_in[i]; break;
            case 1024:   bi = (const float*)d_in[i]; break;
            default: break;
        }
    }
    if (!x)  x  = (const float*)d_in[0];
    if (!wx) wx = (const float*)d_in[1];
    if (!wh) wh = (const float*)d_in[2];
    if (!bi) bi = (const float*)d_in[3];

    cudaFuncSetAttribute(lstm_cluster_kernel,
                         cudaFuncAttributeMaxDynamicSharedMemorySize, SMEM_BYTES);

    lstm_cluster_kernel<<<BB / BPC * CLS, NTHR, SMEM_BYTES>>>(
        x, wx, wh, bi, (float*)d_out, out_size);
}

// round 11
// speedup vs baseline: 1.7483x; 1.3148x over previous
#include <cuda_runtime.h>
#include <cuda_bf16.h>
#include <cstdint>
#include <cstddef>

// Problem constants
#define BB   128
#define TT   2048
#define UU   256
#define CLS  8        // cluster size (u-split)
#define BPC  8        // batches per cluster
#define UCTA 32       // u per CTA
#define COLS 128      // z columns per CTA; c = g*32 + u (gate-major)
#define NTHR 256      // 8 warps; warp w owns m-tile rows [16w,16w+16)

#define H_BLOCK_BYTES (BPC*UCTA*4)       // 1 KB per rank per step
#define TX_BYTES      (CLS*H_BLOCK_BYTES)

typedef unsigned long long ull;

__device__ __forceinline__ uint32_t smem_u32(const void* p) {
    uint32_t a;
    asm("{ .reg .u64 t; cvta.to.shared.u64 t, %1; cvt.u32.u64 %0, t; }" : "=r"(a) : "l"(p));
    return a;
}

__device__ __forceinline__ void mbar_init(uint32_t mbar, uint32_t cnt) {
    asm volatile("mbarrier.init.shared.b64 [%0], %1;" :: "r"(mbar), "r"(cnt) : "memory");
}
__device__ __forceinline__ void mbar_arrive_expect(uint32_t mbar, uint32_t tx) {
    asm volatile("mbarrier.arrive.expect_tx.shared.b64 _, [%0], %1;"
                 :: "r"(mbar), "r"(tx) : "memory");
}
__device__ __forceinline__ void mbar_wait(uint32_t mbar, uint32_t parity) {
    asm volatile(
        "{\n\t.reg .pred P;\n\t"
        "WL_%=:\n\t"
        "mbarrier.try_wait.parity.acquire.cta.shared::cta.b64 P, [%0], %1, 0x989680;\n\t"
        "@P bra.uni WD_%=;\n\t"
        "bra.uni WL_%=;\n\t"
        "WD_%=:\n\t}" :: "r"(mbar), "r"(parity) : "memory");
}

__device__ __forceinline__ void bulk_copy_to_rank(uint32_t dst_local, uint32_t src,
                                                  uint32_t bytes, uint32_t mbar_local,
                                                  uint32_t rank) {
    uint32_t rd, rm;
    asm volatile("mapa.shared::cluster.u32 %0, %1, %2;" : "=r"(rd) : "r"(dst_local), "r"(rank));
    asm volatile("mapa.shared::cluster.u32 %0, %1, %2;" : "=r"(rm) : "r"(mbar_local), "r"(rank));
    asm volatile("cp.async.bulk.shared::cluster.shared::cta.mbarrier::complete_tx::bytes "
                 "[%0], [%1], %2, [%3];"
                 :: "r"(rd), "r"(src), "r"(bytes), "r"(rm) : "memory");
}

// Warp-level bf16 MMA, m16n8k16, fp32 accumulate (arch-neutral, no 'a' feature)
__device__ __forceinline__ void mma_bf16(float& d0, float& d1, float& d2, float& d3,
                                         uint32_t a0, uint32_t a1, uint32_t a2, uint32_t a3,
                                         uint32_t b0, uint32_t b1) {
    asm volatile(
        "mma.sync.aligned.m16n8k16.row.col.f32.bf16.bf16.f32 "
        "{%0,%1,%2,%3}, {%4,%5,%6,%7}, {%8,%9}, {%0,%1,%2,%3};"
        : "+f"(d0), "+f"(d1), "+f"(d2), "+f"(d3)
        : "r"(a0), "r"(a1), "r"(a2), "r"(a3), "r"(b0), "r"(b1));
}

__device__ __forceinline__ uint32_t pack_bf16(float lo_elem, float hi_elem) {
    __nv_bfloat162 p = __floats2bfloat162_rn(lo_elem, hi_elem);  // .x -> low half
    return *(uint32_t*)&p;
}

__device__ __forceinline__ float sigm(float v) { return 1.f / (1.f + __expf(-v)); }
__device__ __forceinline__ float tanh_f(float v) {
    float vv = fminf(fmaxf(v, -15.f), 15.f);
    float e = __expf(-2.f * vv);
    return (1.f - e) / (1.f + e);
}

// B-pack word index: k-step s (0..15), k-pair p (0..7), batch n (0..7), XOR swizzle
#define BPW(s, p, n) (((s) * 8 + (p)) * 8 + ((n) ^ ((s) & 7)))

__global__ void __launch_bounds__(NTHR, 1) __cluster_dims__(CLS, 1, 1)
lstm_hmma_kernel(const float* __restrict__ x,     // [B,T,3]
                 const float* __restrict__ Wx,    // [3,1024]
                 const float* __restrict__ Wh,    // [256,1024]
                 const float* __restrict__ bias,  // [1024]
                 float* __restrict__ out, int out_size)
{
    __shared__ __align__(16) float stg[2][CLS][BPC][UCTA];   // h staging (bulk-copy dst)
    __shared__ __align__(16) float hout[2][BPC][UCTA];       // h out-stage (bulk-copy src)
    __shared__ uint32_t bphi[1024];                          // B bf16-hi packed words
    __shared__ uint32_t bplo[1024];                          // B bf16-lo packed words
    __shared__ float zsm[BPC][132];                          // z staging (padded)
    __shared__ float wxs[3][COLS];
    __shared__ float bis[COLS];
    __shared__ float xss[BPC][4];
    __shared__ __align__(8) ull mbars[3];

    const int tid   = threadIdx.x;
    const int wid   = tid >> 5;
    const int lane  = tid & 31;
    const int crank = blockIdx.x & (CLS - 1);
    const int cid   = blockIdx.x >> 3;
    const int bBase = cid * BPC;
    const int uBase = crank * UCTA;

    const uint32_t mbE0 = smem_u32(&mbars[0]);
    const uint32_t mbE1 = mbE0 + 8;

    // ---- Prologue: A = W^T slice as register-resident MMA fragments (hi/lo) ----
    // Warp w owns rows m in [16w, 16w+16). Fragment thread roles:
    const int g  = lane >> 2;      // group id (row within tile)
    const int tq = lane & 3;       // thread-in-group (k-pair selector)
    uint32_t Ahi[64], Alo[64];
    {
        const int mA = wid * 16 + g;
        const int mB = mA + 8;
        const int gcolA = (mA >> 5) * UU + uBase + (mA & 31);
        const int gcolB = (mB >> 5) * UU + uBase + (mB & 31);
        #pragma unroll
        for (int s = 0; s < 16; ++s) {
            const int k0 = s * 16 + tq * 2;
            float wA0 = Wh[(size_t)(k0)     * 1024 + gcolA];
            float wA1 = Wh[(size_t)(k0 + 1) * 1024 + gcolA];
            float wB0 = Wh[(size_t)(k0)     * 1024 + gcolB];
            float wB1 = Wh[(size_t)(k0 + 1) * 1024 + gcolB];
            float wA8 = Wh[(size_t)(k0 + 8) * 1024 + gcolA];
            float wA9 = Wh[(size_t)(k0 + 9) * 1024 + gcolA];
            float wB8 = Wh[(size_t)(k0 + 8) * 1024 + gcolB];
            float wB9 = Wh[(size_t)(k0 + 9) * 1024 + gcolB];
            // hi fragments
            uint32_t h0 = pack_bf16(wA0, wA1), h1 = pack_bf16(wB0, wB1);
            uint32_t h2 = pack_bf16(wA8, wA9), h3 = pack_bf16(wB8, wB9);
            Ahi[s * 4 + 0] = h0; Ahi[s * 4 + 1] = h1;
            Ahi[s * 4 + 2] = h2; Ahi[s * 4 + 3] = h3;
            // lo residuals
            __nv_bfloat162* ph;
            ph = (__nv_bfloat162*)&h0;
            Alo[s * 4 + 0] = pack_bf16(wA0 - __bfloat162float(ph->x), wA1 - __bfloat162float(ph->y));
            ph = (__nv_bfloat162*)&h1;
            Alo[s * 4 + 1] = pack_bf16(wB0 - __bfloat162float(ph->x), wB1 - __bfloat162float(ph->y));
            ph = (__nv_bfloat162*)&h2;
            Alo[s * 4 + 2] = pack_bf16(wA8 - __bfloat162float(ph->x), wA9 - __bfloat162float(ph->y));
            ph = (__nv_bfloat162*)&h3;
            Alo[s * 4 + 3] = pack_bf16(wB8 - __bfloat162float(ph->x), wB9 - __bfloat162float(ph->y));
        }
    }

    for (int idx = tid; idx < 3 * COLS; idx += NTHR) {
        int f = idx >> 7, cc = idx & 127;
        wxs[f][cc] = Wx[f * 1024 + (cc >> 5) * UU + uBase + (cc & 31)];
    }
    if (tid < COLS) bis[tid] = bias[(tid >> 5) * UU + uBase + (tid & 31)];
    for (int idx = tid; idx < 2 * CLS * BPC * UCTA; idx += NTHR) ((float*)stg)[idx] = 0.f;
    if (tid == 0) {
        mbar_init(mbE0, 1); mbar_init(mbE1, 1);
        mbar_arrive_expect(mbE0, TX_BYTES);
        mbar_arrive_expect(mbE1, TX_BYTES);
    }
    __syncthreads();
    asm volatile("barrier.cluster.arrive.aligned;" ::: "memory");
    asm volatile("barrier.cluster.wait.aligned;"   ::: "memory");

    // Convert mapping: thread -> (source rank r, k-lane); covers k = 0..255
    const int cvr = tid >> 5;                 // rank 0..7
    const int cvk = cvr * 32 + lane;          // global k
    const int cvs = cvk >> 4;                 // k-step
    const int cvp = (cvk >> 1) & 7;           // k-pair
    const bool cvstore = ((lane & 1) == 0);

    // Epilogue mapping: (batch eb, unit eu)
    const int eb = wid;
    const int eu = lane;
    const int gu = uBase + eu;
    const int gb = bBase + eb;

    float creg = 0.f, hreg = 0.f;
    uint32_t ph0 = 0, ph1 = 0;

    for (int t = 0; t < TT; ++t) {
        const int pp = t & 1;
        const int np = pp ^ 1;

        // x prefetch (24 threads)
        float xv = 0.f; int xb = 0, xf = 0;
        if (tid < BPC * 3) {
            xb = tid / 3; xf = tid - xb * 3;
            xv = x[((size_t)(bBase + xb) * TT + t) * 3 + xf];
        }

        // wait for staging[pp]; re-arm for next phase
        if (t > 0) {
            if (tid == 0) {
                uint32_t mb = pp ? mbE1 : mbE0;
                mbar_wait(mb, pp ? ph1 : ph0);
                mbar_arrive_expect(mb, TX_BYTES);
            }
            if (pp) ph1 ^= 1; else ph0 ^= 1;
        }
        if (tid < BPC * 3) xss[xb][xf] = xv;
        __syncthreads();   // staging + xss released

        // ---- convert staging[pp] -> packed bf16 hi/lo B words ----
        {
            const float* src = &stg[pp][cvr][0][lane];
            #pragma unroll
            for (int b = 0; b < BPC; ++b) {
                float v  = src[b * UCTA];
                float vo = __shfl_xor_sync(0xFFFFFFFFu, v, 1);
                if (cvstore) {
                    // k even lane: pair = (mine @ k, partner @ k+1)
                    uint32_t hiw = pack_bf16(v, vo);
                    __nv_bfloat162* ph2 = (__nv_bfloat162*)&hiw;
                    uint32_t low = pack_bf16(v - __bfloat162float(ph2->x),
                                             vo - __bfloat162float(ph2->y));
                    int wi = BPW(cvs, cvp, b);
                    bphi[wi] = hiw;
                    bplo[wi] = low;
                }
            }
        }
        __syncthreads();   // B ready

        // ---- MMA: D[16w..,8] = Ahi*Bhi + Alo*Bhi + Ahi*Blo (fp32 regs) ----
        float d0 = 0.f, d1 = 0.f, d2 = 0.f, d3 = 0.f;
        #pragma unroll
        for (int s = 0; s < 16; ++s) {
            const int nx = g ^ (s & 7);
            uint32_t bh0 = bphi[(s * 8 + tq) * 8 + nx];
            uint32_t bh1 = bphi[(s * 8 + tq + 4) * 8 + nx];
            uint32_t bl0 = bplo[(s * 8 + tq) * 8 + nx];
            uint32_t bl1 = bplo[(s * 8 + tq + 4) * 8 + nx];
            mma_bf16(d0, d1, d2, d3,
                     Ahi[s*4+0], Ahi[s*4+1], Ahi[s*4+2], Ahi[s*4+3], bh0, bh1);
            mma_bf16(d0, d1, d2, d3,
                     Alo[s*4+0], Alo[s*4+1], Alo[s*4+2], Alo[s*4+3], bh0, bh1);
            mma_bf16(d0, d1, d2, d3,
                     Ahi[s*4+0], Ahi[s*4+1], Ahi[s*4+2], Ahi[s*4+3], bl0, bl1);
        }
        // D frag -> zsm: d0=(row g, n=tq*2) d1=(g, tq*2+1) d2=(g+8, tq*2) d3=(g+8, tq*2+1)
        {
            const int c0 = wid * 16 + g;
            zsm[tq * 2 + 0][c0]     = d0;
            zsm[tq * 2 + 1][c0]     = d1;
            zsm[tq * 2 + 0][c0 + 8] = d2;
            zsm[tq * 2 + 1][c0 + 8] = d3;
        }
        __syncthreads();   // zsm ready

        // ---- epilogue: fp32 gates + state + staging ----
        {
            float x0 = xss[eb][0], x1 = xss[eb][1], x2 = xss[eb][2];
            float zg[4];
            #pragma unroll
            for (int gg = 0; gg < 4; ++gg) {
                int cc = gg * 32 + eu;
                zg[gg] = zsm[eb][cc] + bis[cc]
                       + x0 * wxs[0][cc] + x1 * wxs[1][cc] + x2 * wxs[2][cc];
            }
            float ig = sigm(zg[0]);
            float fg = sigm(zg[1]);
            float gv = tanh_f(zg[2]);
            float og = sigm(zg[3]);
            creg = fg * creg + ig * gv;
            hreg = og * tanh_f(creg);

            hout[np][eb][eu] = hreg;
            out[((size_t)gb * TT + t) * UU + gu] = hreg;
        }
        __syncthreads();   // hout staged

        // ---- broadcast our 1KB h block to all 8 CTAs' staging[np] ----
        if (tid == 0) {
            asm volatile("fence.proxy.async.shared::cta;" ::: "memory");
            uint32_t src = smem_u32(&hout[np][0][0]);
            uint32_t dst = smem_u32(&stg[np][crank][0][0]);
            uint32_t mbn = np ? mbE1 : mbE0;
            #pragma unroll
            for (uint32_t r = 0; r < CLS; ++r)
                bulk_copy_to_rank(dst, src, H_BLOCK_BYTES, mbn, r);
        }
    }

    // keep cluster alive until last bulk copies land
    asm volatile("barrier.cluster.arrive.aligned;" ::: "memory");
    asm volatile("barrier.cluster.wait.aligned;"   ::: "memory");

    if (out_size >= BB * TT * UU + 2 * BB * UU) {
        size_t b0 = (size_t)BB * TT * UU;
        out[b0 + (size_t)gb * UU + gu] = hreg;
        out[b0 + (size_t)BB * UU + (size_t)gb * UU + gu] = creg;
    }
}

extern "C" void kernel_launch(void* const* d_in, const int* in_sizes, int n_in,
                              void* d_out, int out_size)
{
    const float* x  = nullptr;  // 786432
    const float* wx = nullptr;  // 3072
    const float* wh = nullptr;  // 262144
    const float* bi = nullptr;  // 1024
    for (int i = 0; i < n_in; ++i) {
        switch (in_sizes[i]) {
            case 786432: x  = (const float*)d_in[i]; break;
            case 3072:   wx = (const float*)d_in[i]; break;
            case 262144: wh = (const float*)d_in[i]; break;
            case 1024:   bi = (const float*)d_in[i]; break;
            default: break;
        }
    }
    if (!x)  x  = (const float*)d_in[0];
    if (!wx) wx = (const float*)d_in[1];
    if (!wh) wh = (const float*)d_in[2];
    if (!bi) bi = (const float*)d_in[3];

    lstm_hmma_kernel<<<BB / BPC * CLS, NTHR>>>(
        x, wx, wh, bi, (float*)d_out, out_size);
}

// round 12
// speedup vs baseline: 2.2165x; 1.2678x over previous
#include <cuda_runtime.h>
#include <cuda_bf16.h>
#include <cstdint>
#include <cstddef>

// Problem constants
#define BB   128
#define TT   2048
#define UU   256
#define CLS  8        // cluster size (u-split)
#define BPC  8        // batches per cluster
#define UCTA 32       // u per CTA
#define COLS 128      // z columns per CTA; c = g*32 + u (gate-major)
#define NTHR 256      // 8 warps; warp w owns m-tile rows [16w,16w+16)

#define H_BLOCK_BYTES 1024               // 256 packed words per rank per step
#define TX_BYTES      (CLS*H_BLOCK_BYTES)

typedef unsigned long long ull;

__device__ __forceinline__ uint32_t smem_u32(const void* p) {
    uint32_t a;
    asm("{ .reg .u64 t; cvta.to.shared.u64 t, %1; cvt.u32.u64 %0, t; }" : "=r"(a) : "l"(p));
    return a;
}

__device__ __forceinline__ void mbar_init(uint32_t mbar, uint32_t cnt) {
    asm volatile("mbarrier.init.shared.b64 [%0], %1;" :: "r"(mbar), "r"(cnt) : "memory");
}
__device__ __forceinline__ void mbar_arrive_expect(uint32_t mbar, uint32_t tx) {
    asm volatile("mbarrier.arrive.expect_tx.shared.b64 _, [%0], %1;"
                 :: "r"(mbar), "r"(tx) : "memory");
}
__device__ __forceinline__ void mbar_wait(uint32_t mbar, uint32_t parity) {
    asm volatile(
        "{\n\t.reg .pred P;\n\t"
        "WL_%=:\n\t"
        "mbarrier.try_wait.parity.acquire.cta.shared::cta.b64 P, [%0], %1, 0x989680;\n\t"
        "@P bra.uni WD_%=;\n\t"
        "bra.uni WL_%=;\n\t"
        "WD_%=:\n\t}" :: "r"(mbar), "r"(parity) : "memory");
}

__device__ __forceinline__ void bulk_copy_to_rank(uint32_t dst_local, uint32_t src,
                                                  uint32_t bytes, uint32_t mbar_local,
                                                  uint32_t rank) {
    uint32_t rd, rm;
    asm volatile("mapa.shared::cluster.u32 %0, %1, %2;" : "=r"(rd) : "r"(dst_local), "r"(rank));
    asm volatile("mapa.shared::cluster.u32 %0, %1, %2;" : "=r"(rm) : "r"(mbar_local), "r"(rank));
    asm volatile("cp.async.bulk.shared::cluster.shared::cta.mbarrier::complete_tx::bytes "
                 "[%0], [%1], %2, [%3];"
                 :: "r"(rd), "r"(src), "r"(bytes), "r"(rm) : "memory");
}

// Warp-level bf16 MMA, m16n8k16, fp32 accumulate
__device__ __forceinline__ void mma_bf16(float& d0, float& d1, float& d2, float& d3,
                                         uint32_t a0, uint32_t a1, uint32_t a2, uint32_t a3,
                                         uint32_t b0, uint32_t b1) {
    asm volatile(
        "mma.sync.aligned.m16n8k16.row.col.f32.bf16.bf16.f32 "
        "{%0,%1,%2,%3}, {%4,%5,%6,%7}, {%8,%9}, {%0,%1,%2,%3};"
        : "+f"(d0), "+f"(d1), "+f"(d2), "+f"(d3)
        : "r"(a0), "r"(a1), "r"(a2), "r"(a3), "r"(b0), "r"(b1));
}

__device__ __forceinline__ uint32_t pack_bf16(float lo_elem, float hi_elem) {
    __nv_bfloat162 p = __floats2bfloat162_rn(lo_elem, hi_elem);  // .x -> low half
    return *(uint32_t*)&p;
}

__device__ __forceinline__ float sigm(float v) { return 1.f / (1.f + __expf(-v)); }
__device__ __forceinline__ float tanh_f(float v) {
    float vv = fminf(fmaxf(v, -15.f), 15.f);
    float e = __expf(-2.f * vv);
    return (1.f - e) / (1.f + e);
}

// B operand word layout (per phase): [s(16)][hl(2)][p&3(4)][n(8)][p>>2(2)]
//   word = s*128 + hl*64 + (p&3)*16 + n*2 + (p>>2)
// Rank r's contribution: s in {2r, 2r+1} -> words [r*256, r*256+256) contiguous (1 KB).
// Consumer thread (g = lane>>2, tq = lane&3), step s:
//   hi pair (p=tq, p=tq+4) = b64 at word s*128 + tq*16 + g*2
//   lo pair               = b64 at word s*128 + 64 + tq*16 + g*2

__global__ void __launch_bounds__(NTHR, 1) __cluster_dims__(CLS, 1, 1)
lstm_hmma_kernel(const float* __restrict__ x,     // [B,T,3]
                 const float* __restrict__ Wx,    // [3,1024]
                 const float* __restrict__ Wh,    // [256,1024]
                 const float* __restrict__ bias,  // [1024]
                 float* __restrict__ out, int out_size)
{
    __shared__ __align__(16) uint32_t bp[2][2048];      // B operand, double-buffered (16 KB)
    __shared__ __align__(16) uint32_t hstage[2][256];   // packed h out-stage (2 KB)
    __shared__ float zsm[BPC][132];                     // z staging (padded)
    __shared__ float wxs[3][COLS];
    __shared__ float bis[COLS];
    __shared__ float xss[BPC][4];
    __shared__ __align__(8) ull mbars[2];

    const int tid   = threadIdx.x;
    const int wid   = tid >> 5;
    const int lane  = tid & 31;
    const int crank = blockIdx.x & (CLS - 1);
    const int cid   = blockIdx.x >> 3;
    const int bBase = cid * BPC;
    const int uBase = crank * UCTA;

    const uint32_t mbE0 = smem_u32(&mbars[0]);
    const uint32_t mbE1 = mbE0 + 8;

    // ---- Prologue: A = W^T slice as register-resident fragments (hi/lo) ----
    const int g  = lane >> 2;
    const int tq = lane & 3;
    uint32_t Ahi[64], Alo[64];
    {
        const int mA = wid * 16 + g;
        const int mB = mA + 8;
        const int gcolA = (mA >> 5) * UU + uBase + (mA & 31);
        const int gcolB = (mB >> 5) * UU + uBase + (mB & 31);
        #pragma unroll
        for (int s = 0; s < 16; ++s) {
            const int k0 = s * 16 + tq * 2;
            float wA0 = Wh[(size_t)(k0)     * 1024 + gcolA];
            float wA1 = Wh[(size_t)(k0 + 1) * 1024 + gcolA];
            float wB0 = Wh[(size_t)(k0)     * 1024 + gcolB];
            float wB1 = Wh[(size_t)(k0 + 1) * 1024 + gcolB];
            float wA8 = Wh[(size_t)(k0 + 8) * 1024 + gcolA];
            float wA9 = Wh[(size_t)(k0 + 9) * 1024 + gcolA];
            float wB8 = Wh[(size_t)(k0 + 8) * 1024 + gcolB];
            float wB9 = Wh[(size_t)(k0 + 9) * 1024 + gcolB];
            uint32_t h0 = pack_bf16(wA0, wA1), h1 = pack_bf16(wB0, wB1);
            uint32_t h2 = pack_bf16(wA8, wA9), h3 = pack_bf16(wB8, wB9);
            Ahi[s * 4 + 0] = h0; Ahi[s * 4 + 1] = h1;
            Ahi[s * 4 + 2] = h2; Ahi[s * 4 + 3] = h3;
            __nv_bfloat162* ph;
            ph = (__nv_bfloat162*)&h0;
            Alo[s * 4 + 0] = pack_bf16(wA0 - __bfloat162float(ph->x), wA1 - __bfloat162float(ph->y));
            ph = (__nv_bfloat162*)&h1;
            Alo[s * 4 + 1] = pack_bf16(wB0 - __bfloat162float(ph->x), wB1 - __bfloat162float(ph->y));
            ph = (__nv_bfloat162*)&h2;
            Alo[s * 4 + 2] = pack_bf16(wA8 - __bfloat162float(ph->x), wA9 - __bfloat162float(ph->y));
            ph = (__nv_bfloat162*)&h3;
            Alo[s * 4 + 3] = pack_bf16(wB8 - __bfloat162float(ph->x), wB9 - __bfloat162float(ph->y));
        }
    }

    for (int idx = tid; idx < 3 * COLS; idx += NTHR) {
        int f = idx >> 7, cc = idx & 127;
        wxs[f][cc] = Wx[f * 1024 + (cc >> 5) * UU + uBase + (cc & 31)];
    }
    if (tid < COLS) bis[tid] = bias[(tid >> 5) * UU + uBase + (tid & 31)];
    for (int idx = tid; idx < 2 * 2048; idx += NTHR) ((uint32_t*)bp)[idx] = 0u;
    if (tid == 0) {
        mbar_init(mbE0, 1); mbar_init(mbE1, 1);
        mbar_arrive_expect(mbE0, TX_BYTES);
        mbar_arrive_expect(mbE1, TX_BYTES);
    }
    __syncthreads();
    asm volatile("barrier.cluster.arrive.aligned;" ::: "memory");
    asm volatile("barrier.cluster.wait.aligned;"   ::: "memory");

    // Epilogue mapping: (batch eb = wid, unit eu = lane)
    const int eb = wid;
    const int eu = lane;
    const int gu = uBase + eu;
    const int gb = bBase + eb;
    // producer pack indices (even eu lanes)
    const int psloc = eu >> 4;
    const int pp_   = (eu >> 1) & 7;
    const int pwbase = psloc * 128 + (pp_ & 3) * 16 + eb * 2 + (pp_ >> 2);

    // copy addresses (used by lane 0 of each warp; rank = wid)
    const uint32_t bp_s  = smem_u32(&bp[0][0]);
    const uint32_t stg_s = smem_u32(&hstage[0][0]);

    float creg = 0.f, hreg = 0.f;
    uint32_t ph0 = 0, ph1 = 0;

    for (int t = 0; t < TT; ++t) {
        const int pp = t & 1;
        const int np = pp ^ 1;

        // x prefetch (24 threads)
        float xv = 0.f; int xb = 0, xf = 0;
        if (tid < BPC * 3) {
            xb = tid / 3; xf = tid - xb * 3;
            xv = x[((size_t)(bBase + xb) * TT + t) * 3 + xf];
        }

        // wait for B[pp] (8 bulk copies from step t-1); re-arm
        if (t > 0) {
            if (tid == 0) {
                uint32_t mb = pp ? mbE1 : mbE0;
                mbar_wait(mb, pp ? ph1 : ph0);
                mbar_arrive_expect(mb, TX_BYTES);
            }
            if (pp) ph1 ^= 1; else ph0 ^= 1;
        }
        if (tid < BPC * 3) xss[xb][xf] = xv;
        __syncthreads();   // bar1: B operand released

        // ---- MMA: 6 independent accumulator chains (3 terms x 2 s-halves) ----
        float ac[6][4];
        #pragma unroll
        for (int i = 0; i < 6; ++i) {
            ac[i][0] = 0.f; ac[i][1] = 0.f; ac[i][2] = 0.f; ac[i][3] = 0.f;
        }
        {
            const uint32_t* bb = &bp[pp][0];
            const int loff = tq * 16 + g * 2;
            #pragma unroll
            for (int s = 0; s < 16; ++s) {
                ull hp = *(const ull*)(bb + s * 128 + loff);
                ull lp = *(const ull*)(bb + s * 128 + 64 + loff);
                uint32_t bh0 = (uint32_t)hp, bh1 = (uint32_t)(hp >> 32);
                uint32_t bl0 = (uint32_t)lp, bl1 = (uint32_t)(lp >> 32);
                const int si = (s >> 3) * 3;
                mma_bf16(ac[si][0], ac[si][1], ac[si][2], ac[si][3],
                         Ahi[s*4+0], Ahi[s*4+1], Ahi[s*4+2], Ahi[s*4+3], bh0, bh1);
                mma_bf16(ac[si+1][0], ac[si+1][1], ac[si+1][2], ac[si+1][3],
                         Alo[s*4+0], Alo[s*4+1], Alo[s*4+2], Alo[s*4+3], bh0, bh1);
                mma_bf16(ac[si+2][0], ac[si+2][1], ac[si+2][2], ac[si+2][3],
                         Ahi[s*4+0], Ahi[s*4+1], Ahi[s*4+2], Ahi[s*4+3], bl0, bl1);
            }
        }
        {
            float d0 = ac[0][0]+ac[1][0]+ac[2][0]+ac[3][0]+ac[4][0]+ac[5][0];
            float d1 = ac[0][1]+ac[1][1]+ac[2][1]+ac[3][1]+ac[4][1]+ac[5][1];
            float d2 = ac[0][2]+ac[1][2]+ac[2][2]+ac[3][2]+ac[4][2]+ac[5][2];
            float d3 = ac[0][3]+ac[1][3]+ac[2][3]+ac[3][3]+ac[4][3]+ac[5][3];
            const int c0 = wid * 16 + g;
            zsm[tq * 2 + 0][c0]     = d0;
            zsm[tq * 2 + 1][c0]     = d1;
            zsm[tq * 2 + 0][c0 + 8] = d2;
            zsm[tq * 2 + 1][c0 + 8] = d3;
        }
        __syncthreads();   // bar2: zsm ready

        // ---- epilogue: gates + state + producer-side B packing ----
        {
            float x0 = xss[eb][0], x1 = xss[eb][1], x2 = xss[eb][2];
            float zg[4];
            #pragma unroll
            for (int gg = 0; gg < 4; ++gg) {
                int cc = gg * 32 + eu;
                zg[gg] = zsm[eb][cc] + bis[cc]
                       + x0 * wxs[0][cc] + x1 * wxs[1][cc] + x2 * wxs[2][cc];
            }
            float ig = sigm(zg[0]);
            float fg = sigm(zg[1]);
            float gv = tanh_f(zg[2]);
            float og = sigm(zg[3]);
            creg = fg * creg + ig * gv;
            hreg = og * tanh_f(creg);

            // pack (h[eu], h[eu+1]) into B-fragment words (even lanes)
            float hn = __shfl_xor_sync(0xFFFFFFFFu, hreg, 1);
            if ((eu & 1) == 0) {
                uint32_t hiw = pack_bf16(hreg, hn);
                __nv_bfloat162* ph2 = (__nv_bfloat162*)&hiw;
                uint32_t low = pack_bf16(hreg - __bfloat162float(ph2->x),
                                         hn   - __bfloat162float(ph2->y));
                hstage[np][pwbase]      = hiw;
                hstage[np][pwbase + 64] = low;
            }
            out[((size_t)gb * TT + t) * UU + gu] = hreg;
        }
        __syncthreads();   // bar3: hstage staged

        // ---- parallel broadcast: warp w's lane 0 copies our 1 KB block to rank w ----
        if (lane == 0) {
            asm volatile("fence.proxy.async.shared::cta;" ::: "memory");
            uint32_t src = stg_s + np * H_BLOCK_BYTES;
            uint32_t dst = bp_s + np * 8192 + crank * H_BLOCK_BYTES;
            uint32_t mbn = np ? mbE1 : mbE0;
            bulk_copy_to_rank(dst, src, H_BLOCK_BYTES, mbn, (uint32_t)wid);
        }
    }

    // keep cluster alive until last bulk copies land
    asm volatile("barrier.cluster.arrive.aligned;" ::: "memory");
    asm volatile("barrier.cluster.wait.aligned;"   ::: "memory");

    if (out_size >= BB * TT * UU + 2 * BB * UU) {
        size_t b0 = (size_t)BB * TT * UU;
        out[b0 + (size_t)gb * UU + gu] = hreg;
        out[b0 + (size_t)BB * UU + (size_t)gb * UU + gu] = creg;
    }
}

extern "C" void kernel_launch(void* const* d_in, const int* in_sizes, int n_in,
                              void* d_out, int out_size)
{
    const float* x  = nullptr;  // 786432
    const float* wx = nullptr;  // 3072
    const float* wh = nullptr;  // 262144
    const float* bi = nullptr;  // 1024
    for (int i = 0; i < n_in; ++i) {
        switch (in_sizes[i]) {
            case 786432: x  = (const float*)d_in[i]; break;
            case 3072:   wx = (const float*)d_in[i]; break;
            case 262144: wh = (const float*)d_in[i]; break;
            case 1024:   bi = (const float*)d_in[i]; break;
            default: break;
        }
    }
    if (!x)  x  = (const float*)d_in[0];
    if (!wx) wx = (const float*)d_in[1];
    if (!wh) wh = (const float*)d_in[2];
    if (!bi) bi = (const float*)d_in[3];

    lstm_hmma_kernel<<<BB / BPC * CLS, NTHR>>>(
        x, wx, wh, bi, (float*)d_out, out_size);
}